// round 3
// baseline (speedup 1.0000x reference)
#include <cuda_runtime.h>
#include <cuda_bf16.h>
#include <cstdint>

#define Bq 8
#define Nq 2048
#define Dq 128
#define NEGV (-9e15f)
#define ALPHA 0.2f

// ---------------- scratch (device globals; no allocations allowed) ----------
__device__ float g_w1[Dq];
__device__ float g_w2[Dq];
__device__ float g_Wh1[Bq * Nq];
__device__ float g_Wh2[Bq * Nq];
__device__ __nv_bfloat16 g_Whb[(size_t)Bq * Nq * Dq];   // 4 MB bf16 Wh

// ---------------- K0: w1 = W @ a[:d], w2 = W @ a[d:] ------------------------
__global__ void k_wa(const float* __restrict__ W, const float* __restrict__ a) {
    int k = threadIdx.x;                 // 128 threads
    float s1 = 0.f, s2 = 0.f;
    #pragma unroll 8
    for (int j = 0; j < Dq; j++) {
        float w = W[k * Dq + j];
        s1 += w * a[j];
        s2 += w * a[Dq + j];
    }
    g_w1[k] = s1;
    g_w2[k] = s2;
}

// ---------------- K1: Wh1[row] = h[row]·w1, Wh2[row] = h[row]·w2 ------------
__global__ void __launch_bounds__(256) k_wh12(const float* __restrict__ h) {
    int row  = blockIdx.x * 8 + (threadIdx.x >> 5);
    int lane = threadIdx.x & 31;
    float4 v  = *(const float4*)&h[(size_t)row * Dq + lane * 4];
    float4 u1 = *(const float4*)&g_w1[lane * 4];
    float4 u2 = *(const float4*)&g_w2[lane * 4];
    float s1 = v.x * u1.x + v.y * u1.y + v.z * u1.z + v.w * u1.w;
    float s2 = v.x * u2.x + v.y * u2.y + v.z * u2.z + v.w * u2.w;
    #pragma unroll
    for (int o = 16; o; o >>= 1) {
        s1 += __shfl_xor_sync(0xffffffffu, s1, o);
        s2 += __shfl_xor_sync(0xffffffffu, s2, o);
    }
    if (lane == 0) { g_Wh1[row] = s1; g_Wh2[row] = s2; }
}

// ---------------- K2: Wh = h @ W (fp32 compute) -> bf16 scratch -------------
#define TM2 128
__global__ void __launch_bounds__(256) k_wh(const float* __restrict__ h,
                                            const float* __restrict__ W) {
    __shared__ float As[32][TM2 + 4];   // [k][m] transposed h chunk
    __shared__ float Bs[32][Dq + 4];    // [k][c] W chunk
    const int m0  = blockIdx.x * TM2;
    const int tid = threadIdx.x;
    const int tx  = tid & 15, ty = tid >> 4;

    float acc[8][8];
    #pragma unroll
    for (int i = 0; i < 8; i++)
        #pragma unroll
        for (int j = 0; j < 8; j++) acc[i][j] = 0.f;

    for (int kc = 0; kc < Dq; kc += 32) {
        // load h chunk transposed: 128 rows x 32 k  (1024 float4)
        for (int i = tid; i < 128 * 8; i += 256) {
            int m = i >> 3, f = i & 7;
            float4 v = *(const float4*)&h[(size_t)(m0 + m) * Dq + kc + f * 4];
            As[f * 4 + 0][m] = v.x;
            As[f * 4 + 1][m] = v.y;
            As[f * 4 + 2][m] = v.z;
            As[f * 4 + 3][m] = v.w;
        }
        // load W chunk: 32 rows x 128 cols (1024 float4)
        for (int i = tid; i < 32 * 32; i += 256) {
            int k = i >> 5, f = i & 31;
            *(float4*)&Bs[k][f * 4] = *(const float4*)&W[(size_t)(kc + k) * Dq + f * 4];
        }
        __syncthreads();
        #pragma unroll 8
        for (int k = 0; k < 32; k++) {
            float a8[8], b8[8];
            *(float4*)&a8[0] = *(const float4*)&As[k][ty * 8];
            *(float4*)&a8[4] = *(const float4*)&As[k][ty * 8 + 4];
            *(float4*)&b8[0] = *(const float4*)&Bs[k][tx * 8];
            *(float4*)&b8[4] = *(const float4*)&Bs[k][tx * 8 + 4];
            #pragma unroll
            for (int i = 0; i < 8; i++)
                #pragma unroll
                for (int j = 0; j < 8; j++)
                    acc[i][j] += a8[i] * b8[j];
        }
        __syncthreads();
    }
    // store as bf16
    #pragma unroll
    for (int i = 0; i < 8; i++) {
        int row = m0 + ty * 8 + i;
        __nv_bfloat162* dst = (__nv_bfloat162*)(g_Whb + (size_t)row * Dq + tx * 8);
        #pragma unroll
        for (int j = 0; j < 4; j++) {
            __nv_bfloat162 t;
            t.x = __float2bfloat16_rn(acc[i][2 * j]);
            t.y = __float2bfloat16_rn(acc[i][2 * j + 1]);
            dst[j] = t;
        }
    }
}

// ---------------- K3: masked leaky-relu scores + row softmax -> attention ---
__global__ void __launch_bounds__(256) k_soft(const int* __restrict__ adj,
                                              float* __restrict__ attn) {
    const int row = blockIdx.x;            // b*N + i
    const int b   = row >> 11;
    const int tid = threadIdx.x;
    __shared__ float redmax[8];
    __shared__ float redsum[8];

    const int*   arow = adj + (size_t)row * Nq;
    const float* wh2  = g_Wh2 + (size_t)b * Nq;
    const float  wh1  = g_Wh1[row];

    int4 a0 = ((const int4*)arow)[tid * 2];
    int4 a1 = ((const int4*)arow)[tid * 2 + 1];
    float4 v0 = ((const float4*)wh2)[tid * 2];
    float4 v1 = ((const float4*)wh2)[tid * 2 + 1];

    float e[8];
    int   msk[8];
    float w2v[8] = {v0.x, v0.y, v0.z, v0.w, v1.x, v1.y, v1.z, v1.w};
    int   av[8]  = {a0.x, a0.y, a0.z, a0.w, a1.x, a1.y, a1.z, a1.w};
    float m = NEGV;
    #pragma unroll
    for (int i = 0; i < 8; i++) {
        float x = wh1 + w2v[i];
        x = x > 0.f ? x : ALPHA * x;
        e[i]   = x;
        msk[i] = av[i] > 0;
        float s = msk[i] ? x : NEGV;
        m = fmaxf(m, s);
    }
    // block max
    #pragma unroll
    for (int o = 16; o; o >>= 1) m = fmaxf(m, __shfl_xor_sync(0xffffffffu, m, o));
    if ((tid & 31) == 0) redmax[tid >> 5] = m;
    __syncthreads();
    m = redmax[0];
    #pragma unroll
    for (int i = 1; i < 8; i++) m = fmaxf(m, redmax[i]);

    float p[8];
    float s = 0.f;
    #pragma unroll
    for (int i = 0; i < 8; i++) {
        p[i] = msk[i] ? __expf(e[i] - m) : 0.f;
        s += p[i];
    }
    #pragma unroll
    for (int o = 16; o; o >>= 1) s += __shfl_xor_sync(0xffffffffu, s, o);
    if ((tid & 31) == 0) redsum[tid >> 5] = s;
    __syncthreads();
    s = redsum[0];
    #pragma unroll
    for (int i = 1; i < 8; i++) s += redsum[i];
    float inv = 1.0f / s;

    float4 o0, o1;
    o0.x = p[0] * inv; o0.y = p[1] * inv; o0.z = p[2] * inv; o0.w = p[3] * inv;
    o1.x = p[4] * inv; o1.y = p[5] * inv; o1.z = p[6] * inv; o1.w = p[7] * inv;
    float* dst = attn + (size_t)row * Nq + tid * 8;
    *(float4*)dst       = o0;
    *(float4*)(dst + 4) = o1;
}

// ---------------- K4: out = h + attention @ Wh  (bf16 mma.sync) -------------
__device__ __forceinline__ void ldmA4(uint32_t* a, uint32_t addr) {
    asm volatile("ldmatrix.sync.aligned.m8n8.x4.shared.b16 {%0,%1,%2,%3}, [%4];"
                 : "=r"(a[0]), "=r"(a[1]), "=r"(a[2]), "=r"(a[3]) : "r"(addr));
}
__device__ __forceinline__ void ldmBt2(uint32_t* b, uint32_t addr) {
    asm volatile("ldmatrix.sync.aligned.m8n8.x2.trans.shared.b16 {%0,%1}, [%2];"
                 : "=r"(b[0]), "=r"(b[1]) : "r"(addr));
}
__device__ __forceinline__ void mma16816(float* c, const uint32_t* a, const uint32_t* b) {
    asm volatile("mma.sync.aligned.m16n8k16.row.col.f32.bf16.bf16.f32 "
                 "{%0,%1,%2,%3}, {%4,%5,%6,%7}, {%8,%9}, {%0,%1,%2,%3};"
                 : "+f"(c[0]), "+f"(c[1]), "+f"(c[2]), "+f"(c[3])
                 : "r"(a[0]), "r"(a[1]), "r"(a[2]), "r"(a[3]), "r"(b[0]), "r"(b[1]));
}

#define TM4 128
#define KC4 32
#define AS_STRIDE 40     // bf16 halves (pad 8) -> 80B row, conflict-free ldmatrix
#define BS_STRIDE 136    // bf16 halves (pad 8)

__global__ void __launch_bounds__(512) k_av(const float* __restrict__ attn,
                                            const float* __restrict__ h,
                                            float* __restrict__ out) {
    __shared__ __nv_bfloat16 As[TM4][AS_STRIDE];  // attention tile (bf16) [m][k]
    __shared__ __nv_bfloat16 Bs[KC4][BS_STRIDE];  // Wh tile [k][c]

    const int tid  = threadIdx.x;
    const int lane = tid & 31;
    const int wid  = tid >> 5;          // 0..15
    const int wy   = wid >> 2;          // 0..3  (m block of 32)
    const int wx   = wid & 3;           // 0..3  (n block of 32)
    const int b    = blockIdx.x >> 4;
    const int mt   = blockIdx.x & 15;

    const float* ab           = attn + ((size_t)b * Nq + mt * TM4) * Nq;
    const __nv_bfloat16* whb  = g_Whb + (size_t)b * Nq * Dq;

    float acc[2][4][4];
    #pragma unroll
    for (int t = 0; t < 2; t++)
        #pragma unroll
        for (int u = 0; u < 4; u++)
            #pragma unroll
            for (int q = 0; q < 4; q++) acc[t][u][q] = 0.f;

    uint32_t as0 = (uint32_t)__cvta_generic_to_shared(&As[0][0]);
    uint32_t bs0 = (uint32_t)__cvta_generic_to_shared(&Bs[0][0]);

    const int i0 = tid, i1 = tid + 512;
    const int r0 = i0 >> 3, f0 = i0 & 7;
    const int r1 = i1 >> 3, f1 = i1 & 7;
    const int brow = tid >> 4;          // 0..31  (B tile row)
    const int bcol = (tid & 15) * 8;    // 0..120 (B tile col, 8 bf16 per thread)

    float4 ra0, ra1;
    uint4  rb;
    // prefetch chunk 0
    ra0 = *(const float4*)&ab[(size_t)r0 * Nq + f0 * 4];
    ra1 = *(const float4*)&ab[(size_t)r1 * Nq + f1 * 4];
    rb  = *(const uint4*)(whb + (size_t)brow * Dq + bcol);

    const int NIT = Nq / KC4;   // 64
    for (int it = 0; it < NIT; it++) {
        // stage registers -> smem
        {
            __nv_bfloat162* p = (__nv_bfloat162*)&As[r0][f0 * 4];
            __nv_bfloat162 t0, t1;
            t0.x = __float2bfloat16_rn(ra0.x); t0.y = __float2bfloat16_rn(ra0.y);
            t1.x = __float2bfloat16_rn(ra0.z); t1.y = __float2bfloat16_rn(ra0.w);
            p[0] = t0; p[1] = t1;
            p = (__nv_bfloat162*)&As[r1][f1 * 4];
            t0.x = __float2bfloat16_rn(ra1.x); t0.y = __float2bfloat16_rn(ra1.y);
            t1.x = __float2bfloat16_rn(ra1.z); t1.y = __float2bfloat16_rn(ra1.w);
            p[0] = t0; p[1] = t1;
            *(uint4*)&Bs[brow][bcol] = rb;
        }
        __syncthreads();
        // prefetch next chunk
        if (it + 1 < NIT) {
            int kc = (it + 1) * KC4;
            ra0 = *(const float4*)&ab[(size_t)r0 * Nq + kc + f0 * 4];
            ra1 = *(const float4*)&ab[(size_t)r1 * Nq + kc + f1 * 4];
            rb  = *(const uint4*)(whb + (size_t)(kc + brow) * Dq + bcol);
        }
        // compute: 2 x k16
        #pragma unroll
        for (int kk = 0; kk < KC4; kk += 16) {
            uint32_t afr[2][4];
            #pragma unroll
            for (int t = 0; t < 2; t++) {
                int m = wy * 32 + t * 16 + (lane & 15);
                uint32_t addr = as0 + ((uint32_t)m * AS_STRIDE + kk + ((lane >> 4) << 3)) * 2u;
                ldmA4(afr[t], addr);
            }
            uint32_t bfr[4][2];
            #pragma unroll
            for (int u = 0; u < 4; u++) {
                int k = kk + (lane & 15);
                int n = wx * 32 + u * 8;
                uint32_t addr = bs0 + ((uint32_t)k * BS_STRIDE + n) * 2u;
                ldmBt2(bfr[u], addr);
            }
            #pragma unroll
            for (int t = 0; t < 2; t++)
                #pragma unroll
                for (int u = 0; u < 4; u++)
                    mma16816(acc[t][u], afr[t], bfr[u]);
        }
        __syncthreads();
    }

    // epilogue: out = h + acc (residual)
    #pragma unroll
    for (int t = 0; t < 2; t++) {
        #pragma unroll
        for (int u = 0; u < 4; u++) {
            int r = mt * TM4 + wy * 32 + t * 16 + (lane >> 2);
            int c = wx * 32 + u * 8 + (lane & 3) * 2;
            size_t base = ((size_t)b * Nq + r) * Dq + c;
            float2 hv = *(const float2*)&h[base];
            float2 ov;
            ov.x = hv.x + acc[t][u][0];
            ov.y = hv.y + acc[t][u][1];
            *(float2*)&out[base] = ov;
            size_t base2 = base + (size_t)8 * Dq;
            float2 hv2 = *(const float2*)&h[base2];
            float2 ov2;
            ov2.x = hv2.x + acc[t][u][2];
            ov2.y = hv2.y + acc[t][u][3];
            *(float2*)&out[base2] = ov2;
        }
    }
}

// ---------------------------------------------------------------------------
extern "C" void kernel_launch(void* const* d_in, const int* in_sizes, int n_in,
                              void* d_out, int out_size) {
    const float* h   = (const float*)d_in[0];
    const int*   adj = (const int*)d_in[1];
    const float* W   = (const float*)d_in[2];
    const float* a   = (const float*)d_in[3];
    float* out  = (float*)d_out;
    float* attn = out + (size_t)Bq * Nq * Dq;   // output layout: [out | attention]

    k_wa  <<<1, 128>>>(W, a);
    k_wh12<<<(Bq * Nq) / 8, 256>>>(h);
    k_wh  <<<(Bq * Nq) / TM2, 256>>>(h, W);
    k_soft<<<Bq * Nq, 256>>>(adj, attn);
    k_av  <<<Bq * (Nq / TM4), 512>>>(attn, h, out);
}

// round 4
// speedup vs baseline: 1.0188x; 1.0188x over previous
#include <cuda_runtime.h>
#include <cuda_bf16.h>
#include <cstdint>

#define Bq 8
#define Nq 2048
#define Dq 128
#define NEGV (-9e15f)
#define ALPHA 0.2f

// ---------------- scratch (device globals; no allocations allowed) ----------
__device__ float g_w1[Dq];
__device__ float g_w2[Dq];
__device__ float g_Wh1[Bq * Nq];
__device__ float g_Wh2[Bq * Nq];
__device__ __nv_bfloat16 g_Whb[(size_t)Bq * Nq * Dq];   // 4 MB bf16 Wh

// ---------------- K0: w1 = W @ a[:d], w2 = W @ a[d:] ------------------------
__global__ void k_wa(const float* __restrict__ W, const float* __restrict__ a) {
    int k = threadIdx.x;                 // 128 threads
    float s1 = 0.f, s2 = 0.f;
    #pragma unroll 8
    for (int j = 0; j < Dq; j++) {
        float w = W[k * Dq + j];
        s1 += w * a[j];
        s2 += w * a[Dq + j];
    }
    g_w1[k] = s1;
    g_w2[k] = s2;
}

// ---------------- K1: Wh1[row] = h[row]·w1, Wh2[row] = h[row]·w2 ------------
__global__ void __launch_bounds__(256) k_wh12(const float* __restrict__ h) {
    int row  = blockIdx.x * 8 + (threadIdx.x >> 5);
    int lane = threadIdx.x & 31;
    float4 v  = *(const float4*)&h[(size_t)row * Dq + lane * 4];
    float4 u1 = *(const float4*)&g_w1[lane * 4];
    float4 u2 = *(const float4*)&g_w2[lane * 4];
    float s1 = v.x * u1.x + v.y * u1.y + v.z * u1.z + v.w * u1.w;
    float s2 = v.x * u2.x + v.y * u2.y + v.z * u2.z + v.w * u2.w;
    #pragma unroll
    for (int o = 16; o; o >>= 1) {
        s1 += __shfl_xor_sync(0xffffffffu, s1, o);
        s2 += __shfl_xor_sync(0xffffffffu, s2, o);
    }
    if (lane == 0) { g_Wh1[row] = s1; g_Wh2[row] = s2; }
}

// ---------------- K2: Wh = h @ W (fp32 compute) -> bf16 scratch -------------
#define TM2 128
__global__ void __launch_bounds__(256) k_wh(const float* __restrict__ h,
                                            const float* __restrict__ W) {
    __shared__ float As[32][TM2 + 4];   // [k][m] transposed h chunk
    __shared__ float Bs[32][Dq + 4];    // [k][c] W chunk
    const int m0  = blockIdx.x * TM2;
    const int tid = threadIdx.x;
    const int tx  = tid & 15, ty = tid >> 4;

    float acc[8][8];
    #pragma unroll
    for (int i = 0; i < 8; i++)
        #pragma unroll
        for (int j = 0; j < 8; j++) acc[i][j] = 0.f;

    for (int kc = 0; kc < Dq; kc += 32) {
        // load h chunk transposed: 128 rows x 32 k  (1024 float4)
        for (int i = tid; i < 128 * 8; i += 256) {
            int m = i >> 3, f = i & 7;
            float4 v = *(const float4*)&h[(size_t)(m0 + m) * Dq + kc + f * 4];
            As[f * 4 + 0][m] = v.x;
            As[f * 4 + 1][m] = v.y;
            As[f * 4 + 2][m] = v.z;
            As[f * 4 + 3][m] = v.w;
        }
        // load W chunk: 32 rows x 128 cols (1024 float4)
        for (int i = tid; i < 32 * 32; i += 256) {
            int k = i >> 5, f = i & 31;
            *(float4*)&Bs[k][f * 4] = *(const float4*)&W[(size_t)(kc + k) * Dq + f * 4];
        }
        __syncthreads();
        #pragma unroll 8
        for (int k = 0; k < 32; k++) {
            float a8[8], b8[8];
            *(float4*)&a8[0] = *(const float4*)&As[k][ty * 8];
            *(float4*)&a8[4] = *(const float4*)&As[k][ty * 8 + 4];
            *(float4*)&b8[0] = *(const float4*)&Bs[k][tx * 8];
            *(float4*)&b8[4] = *(const float4*)&Bs[k][tx * 8 + 4];
            #pragma unroll
            for (int i = 0; i < 8; i++)
                #pragma unroll
                for (int j = 0; j < 8; j++)
                    acc[i][j] += a8[i] * b8[j];
        }
        __syncthreads();
    }
    // store as bf16
    #pragma unroll
    for (int i = 0; i < 8; i++) {
        int row = m0 + ty * 8 + i;
        __nv_bfloat162* dst = (__nv_bfloat162*)(g_Whb + (size_t)row * Dq + tx * 8);
        #pragma unroll
        for (int j = 0; j < 4; j++) {
            __nv_bfloat162 t;
            t.x = __float2bfloat16_rn(acc[i][2 * j]);
            t.y = __float2bfloat16_rn(acc[i][2 * j + 1]);
            dst[j] = t;
        }
    }
}

// ---------------- K3: masked leaky-relu scores + row softmax -> attention ---
__global__ void __launch_bounds__(256) k_soft(const int* __restrict__ adj,
                                              float* __restrict__ attn) {
    const int row = blockIdx.x;            // b*N + i
    const int b   = row >> 11;
    const int tid = threadIdx.x;
    __shared__ float redmax[8];
    __shared__ float redsum[8];

    const int*   arow = adj + (size_t)row * Nq;
    const float* wh2  = g_Wh2 + (size_t)b * Nq;
    const float  wh1  = g_Wh1[row];

    int4 a0 = ((const int4*)arow)[tid * 2];
    int4 a1 = ((const int4*)arow)[tid * 2 + 1];
    float4 v0 = ((const float4*)wh2)[tid * 2];
    float4 v1 = ((const float4*)wh2)[tid * 2 + 1];

    float e[8];
    int   msk[8];
    float w2v[8] = {v0.x, v0.y, v0.z, v0.w, v1.x, v1.y, v1.z, v1.w};
    int   av[8]  = {a0.x, a0.y, a0.z, a0.w, a1.x, a1.y, a1.z, a1.w};
    float m = NEGV;
    #pragma unroll
    for (int i = 0; i < 8; i++) {
        float x = wh1 + w2v[i];
        x = x > 0.f ? x : ALPHA * x;
        e[i]   = x;
        msk[i] = av[i] > 0;
        float s = msk[i] ? x : NEGV;
        m = fmaxf(m, s);
    }
    // block max
    #pragma unroll
    for (int o = 16; o; o >>= 1) m = fmaxf(m, __shfl_xor_sync(0xffffffffu, m, o));
    if ((tid & 31) == 0) redmax[tid >> 5] = m;
    __syncthreads();
    m = redmax[0];
    #pragma unroll
    for (int i = 1; i < 8; i++) m = fmaxf(m, redmax[i]);

    float p[8];
    float s = 0.f;
    #pragma unroll
    for (int i = 0; i < 8; i++) {
        p[i] = msk[i] ? __expf(e[i] - m) : 0.f;
        s += p[i];
    }
    #pragma unroll
    for (int o = 16; o; o >>= 1) s += __shfl_xor_sync(0xffffffffu, s, o);
    if ((tid & 31) == 0) redsum[tid >> 5] = s;
    __syncthreads();
    s = redsum[0];
    #pragma unroll
    for (int i = 1; i < 8; i++) s += redsum[i];
    float inv = 1.0f / s;

    float4 o0, o1;
    o0.x = p[0] * inv; o0.y = p[1] * inv; o0.z = p[2] * inv; o0.w = p[3] * inv;
    o1.x = p[4] * inv; o1.y = p[5] * inv; o1.z = p[6] * inv; o1.w = p[7] * inv;
    float* dst = attn + (size_t)row * Nq + tid * 8;
    *(float4*)dst       = o0;
    *(float4*)(dst + 4) = o1;
}

// ---------------- K4: out = h + attention @ Wh  (bf16 mma.sync) -------------
__device__ __forceinline__ void ldmA4(uint32_t* a, uint32_t addr) {
    asm volatile("ldmatrix.sync.aligned.m8n8.x4.shared.b16 {%0,%1,%2,%3}, [%4];"
                 : "=r"(a[0]), "=r"(a[1]), "=r"(a[2]), "=r"(a[3]) : "r"(addr));
}
__device__ __forceinline__ void ldmBt2(uint32_t* b, uint32_t addr) {
    asm volatile("ldmatrix.sync.aligned.m8n8.x2.trans.shared.b16 {%0,%1}, [%2];"
                 : "=r"(b[0]), "=r"(b[1]) : "r"(addr));
}
__device__ __forceinline__ void mma16816(float* c, const uint32_t* a, const uint32_t* b) {
    asm volatile("mma.sync.aligned.m16n8k16.row.col.f32.bf16.bf16.f32 "
                 "{%0,%1,%2,%3}, {%4,%5,%6,%7}, {%8,%9}, {%0,%1,%2,%3};"
                 : "+f"(c[0]), "+f"(c[1]), "+f"(c[2]), "+f"(c[3])
                 : "r"(a[0]), "r"(a[1]), "r"(a[2]), "r"(a[3]), "r"(b[0]), "r"(b[1]));
}

#define TM4 128
#define KC4 32
#define AS_STRIDE 40     // bf16 halves (pad 8) -> 80B row, conflict-free ldmatrix
#define BS_STRIDE 136    // bf16 halves (pad 8)

__global__ void __launch_bounds__(512) k_av(const float* __restrict__ attn,
                                            const float* __restrict__ h,
                                            float* __restrict__ out) {
    __shared__ __nv_bfloat16 As[TM4][AS_STRIDE];  // attention tile (bf16) [m][k]
    __shared__ __nv_bfloat16 Bs[KC4][BS_STRIDE];  // Wh tile [k][c]

    const int tid  = threadIdx.x;
    const int lane = tid & 31;
    const int wid  = tid >> 5;          // 0..15
    const int wy   = wid >> 2;          // 0..3  (m block of 32)
    const int wx   = wid & 3;           // 0..3  (n block of 32)
    const int b    = blockIdx.x >> 4;
    const int mt   = blockIdx.x & 15;

    const float* ab           = attn + ((size_t)b * Nq + mt * TM4) * Nq;
    const __nv_bfloat16* whb  = g_Whb + (size_t)b * Nq * Dq;

    float acc[2][4][4];
    #pragma unroll
    for (int t = 0; t < 2; t++)
        #pragma unroll
        for (int u = 0; u < 4; u++)
            #pragma unroll
            for (int q = 0; q < 4; q++) acc[t][u][q] = 0.f;

    uint32_t as0 = (uint32_t)__cvta_generic_to_shared(&As[0][0]);
    uint32_t bs0 = (uint32_t)__cvta_generic_to_shared(&Bs[0][0]);

    const int i0 = tid, i1 = tid + 512;
    const int r0 = i0 >> 3, f0 = i0 & 7;
    const int r1 = i1 >> 3, f1 = i1 & 7;
    const int brow = tid >> 4;          // 0..31  (B tile row)
    const int bcol = (tid & 15) * 8;    // 0..120 (B tile col, 8 bf16 per thread)

    float4 ra0, ra1;
    uint4  rb;
    // prefetch chunk 0
    ra0 = *(const float4*)&ab[(size_t)r0 * Nq + f0 * 4];
    ra1 = *(const float4*)&ab[(size_t)r1 * Nq + f1 * 4];
    rb  = *(const uint4*)(whb + (size_t)brow * Dq + bcol);

    const int NIT = Nq / KC4;   // 64
    for (int it = 0; it < NIT; it++) {
        // stage registers -> smem
        {
            __nv_bfloat162* p = (__nv_bfloat162*)&As[r0][f0 * 4];
            __nv_bfloat162 t0, t1;
            t0.x = __float2bfloat16_rn(ra0.x); t0.y = __float2bfloat16_rn(ra0.y);
            t1.x = __float2bfloat16_rn(ra0.z); t1.y = __float2bfloat16_rn(ra0.w);
            p[0] = t0; p[1] = t1;
            p = (__nv_bfloat162*)&As[r1][f1 * 4];
            t0.x = __float2bfloat16_rn(ra1.x); t0.y = __float2bfloat16_rn(ra1.y);
            t1.x = __float2bfloat16_rn(ra1.z); t1.y = __float2bfloat16_rn(ra1.w);
            p[0] = t0; p[1] = t1;
            *(uint4*)&Bs[brow][bcol] = rb;
        }
        __syncthreads();
        // prefetch next chunk
        if (it + 1 < NIT) {
            int kc = (it + 1) * KC4;
            ra0 = *(const float4*)&ab[(size_t)r0 * Nq + kc + f0 * 4];
            ra1 = *(const float4*)&ab[(size_t)r1 * Nq + kc + f1 * 4];
            rb  = *(const uint4*)(whb + (size_t)(kc + brow) * Dq + bcol);
        }
        // compute: 2 x k16
        #pragma unroll
        for (int kk = 0; kk < KC4; kk += 16) {
            uint32_t afr[2][4];
            #pragma unroll
            for (int t = 0; t < 2; t++) {
                int m = wy * 32 + t * 16 + (lane & 15);
                uint32_t addr = as0 + ((uint32_t)m * AS_STRIDE + kk + ((lane >> 4) << 3)) * 2u;
                ldmA4(afr[t], addr);
            }
            uint32_t bfr[4][2];
            #pragma unroll
            for (int u = 0; u < 4; u++) {
                int k = kk + (lane & 15);
                int n = wx * 32 + u * 8;
                uint32_t addr = bs0 + ((uint32_t)k * BS_STRIDE + n) * 2u;
                ldmBt2(bfr[u], addr);
            }
            #pragma unroll
            for (int t = 0; t < 2; t++)
                #pragma unroll
                for (int u = 0; u < 4; u++)
                    mma16816(acc[t][u], afr[t], bfr[u]);
        }
        __syncthreads();
    }

    // epilogue: out = h + acc (residual)
    #pragma unroll
    for (int t = 0; t < 2; t++) {
        #pragma unroll
        for (int u = 0; u < 4; u++) {
            int r = mt * TM4 + wy * 32 + t * 16 + (lane >> 2);
            int c = wx * 32 + u * 8 + (lane & 3) * 2;
            size_t base = ((size_t)b * Nq + r) * Dq + c;
            float2 hv = *(const float2*)&h[base];
            float2 ov;
            ov.x = hv.x + acc[t][u][0];
            ov.y = hv.y + acc[t][u][1];
            *(float2*)&out[base] = ov;
            size_t base2 = base + (size_t)8 * Dq;
            float2 hv2 = *(const float2*)&h[base2];
            float2 ov2;
            ov2.x = hv2.x + acc[t][u][2];
            ov2.y = hv2.y + acc[t][u][3];
            *(float2*)&out[base2] = ov2;
        }
    }
}

// ---------------------------------------------------------------------------
extern "C" void kernel_launch(void* const* d_in, const int* in_sizes, int n_in,
                              void* d_out, int out_size) {
    const float* h   = (const float*)d_in[0];
    const int*   adj = (const int*)d_in[1];
    const float* W   = (const float*)d_in[2];
    const float* a   = (const float*)d_in[3];
    float* out  = (float*)d_out;
    float* attn = out + (size_t)Bq * Nq * Dq;   // output layout: [out | attention]

    k_wa  <<<1, 128>>>(W, a);
    k_wh12<<<(Bq * Nq) / 8, 256>>>(h);
    k_wh  <<<(Bq * Nq) / TM2, 256>>>(h, W);
    k_soft<<<Bq * Nq, 256>>>(adj, attn);
    k_av  <<<Bq * (Nq / TM4), 512>>>(attn, h, out);
}

// round 5
// speedup vs baseline: 1.0190x; 1.0002x over previous
#include <cuda_runtime.h>
#include <cuda_bf16.h>
#include <cstdint>

#define Bq 8
#define Nq 2048
#define Dq 128
#define NEGV (-9e15f)
#define ALPHA 0.2f

// ---------------- scratch (device globals; no allocations allowed) ----------
__device__ float g_w1[Dq];
__device__ float g_w2[Dq];
__device__ float g_Wh1[Bq * Nq];
__device__ float g_Wh2[Bq * Nq];
__device__ __nv_bfloat16 g_Whb[(size_t)Bq * Nq * Dq];   // 4 MB bf16 Wh

// ---------------- K0: w1 = W @ a[:d], w2 = W @ a[d:] ------------------------
__global__ void k_wa(const float* __restrict__ W, const float* __restrict__ a) {
    int k = threadIdx.x;                 // 128 threads
    float s1 = 0.f, s2 = 0.f;
    #pragma unroll 8
    for (int j = 0; j < Dq; j++) {
        float w = W[k * Dq + j];
        s1 += w * a[j];
        s2 += w * a[Dq + j];
    }
    g_w1[k] = s1;
    g_w2[k] = s2;
}

// ---------------- K1: Wh1[row] = h[row]·w1, Wh2[row] = h[row]·w2 ------------
__global__ void __launch_bounds__(256) k_wh12(const float* __restrict__ h) {
    int row  = blockIdx.x * 8 + (threadIdx.x >> 5);
    int lane = threadIdx.x & 31;
    float4 v  = *(const float4*)&h[(size_t)row * Dq + lane * 4];
    float4 u1 = *(const float4*)&g_w1[lane * 4];
    float4 u2 = *(const float4*)&g_w2[lane * 4];
    float s1 = v.x * u1.x + v.y * u1.y + v.z * u1.z + v.w * u1.w;
    float s2 = v.x * u2.x + v.y * u2.y + v.z * u2.z + v.w * u2.w;
    #pragma unroll
    for (int o = 16; o; o >>= 1) {
        s1 += __shfl_xor_sync(0xffffffffu, s1, o);
        s2 += __shfl_xor_sync(0xffffffffu, s2, o);
    }
    if (lane == 0) { g_Wh1[row] = s1; g_Wh2[row] = s2; }
}

// ---------------- K2: Wh = h @ W (fp32 compute) -> bf16 scratch -------------
#define TM2 128
__global__ void __launch_bounds__(256) k_wh(const float* __restrict__ h,
                                            const float* __restrict__ W) {
    __shared__ float As[32][TM2 + 4];   // [k][m] transposed h chunk
    __shared__ float Bs[32][Dq + 4];    // [k][c] W chunk
    const int m0  = blockIdx.x * TM2;
    const int tid = threadIdx.x;
    const int tx  = tid & 15, ty = tid >> 4;

    float acc[8][8];
    #pragma unroll
    for (int i = 0; i < 8; i++)
        #pragma unroll
        for (int j = 0; j < 8; j++) acc[i][j] = 0.f;

    for (int kc = 0; kc < Dq; kc += 32) {
        // load h chunk transposed: 128 rows x 32 k  (1024 float4)
        for (int i = tid; i < 128 * 8; i += 256) {
            int m = i >> 3, f = i & 7;
            float4 v = *(const float4*)&h[(size_t)(m0 + m) * Dq + kc + f * 4];
            As[f * 4 + 0][m] = v.x;
            As[f * 4 + 1][m] = v.y;
            As[f * 4 + 2][m] = v.z;
            As[f * 4 + 3][m] = v.w;
        }
        // load W chunk: 32 rows x 128 cols (1024 float4)
        for (int i = tid; i < 32 * 32; i += 256) {
            int k = i >> 5, f = i & 31;
            *(float4*)&Bs[k][f * 4] = *(const float4*)&W[(size_t)(kc + k) * Dq + f * 4];
        }
        __syncthreads();
        #pragma unroll 8
        for (int k = 0; k < 32; k++) {
            float a8[8], b8[8];
            *(float4*)&a8[0] = *(const float4*)&As[k][ty * 8];
            *(float4*)&a8[4] = *(const float4*)&As[k][ty * 8 + 4];
            *(float4*)&b8[0] = *(const float4*)&Bs[k][tx * 8];
            *(float4*)&b8[4] = *(const float4*)&Bs[k][tx * 8 + 4];
            #pragma unroll
            for (int i = 0; i < 8; i++)
                #pragma unroll
                for (int j = 0; j < 8; j++)
                    acc[i][j] += a8[i] * b8[j];
        }
        __syncthreads();
    }
    // store as bf16
    #pragma unroll
    for (int i = 0; i < 8; i++) {
        int row = m0 + ty * 8 + i;
        __nv_bfloat162* dst = (__nv_bfloat162*)(g_Whb + (size_t)row * Dq + tx * 8);
        #pragma unroll
        for (int j = 0; j < 4; j++) {
            __nv_bfloat162 t;
            t.x = __float2bfloat16_rn(acc[i][2 * j]);
            t.y = __float2bfloat16_rn(acc[i][2 * j + 1]);
            dst[j] = t;
        }
    }
}

// ---------------- K3: masked leaky-relu scores + row softmax -> attention ---
__global__ void __launch_bounds__(256) k_soft(const int* __restrict__ adj,
                                              float* __restrict__ attn) {
    const int row = blockIdx.x;            // b*N + i
    const int b   = row >> 11;
    const int tid = threadIdx.x;
    __shared__ float redmax[8];
    __shared__ float redsum[8];

    const int*   arow = adj + (size_t)row * Nq;
    const float* wh2  = g_Wh2 + (size_t)b * Nq;
    const float  wh1  = g_Wh1[row];

    int4 a0 = ((const int4*)arow)[tid * 2];
    int4 a1 = ((const int4*)arow)[tid * 2 + 1];
    float4 v0 = ((const float4*)wh2)[tid * 2];
    float4 v1 = ((const float4*)wh2)[tid * 2 + 1];

    float e[8];
    int   msk[8];
    float w2v[8] = {v0.x, v0.y, v0.z, v0.w, v1.x, v1.y, v1.z, v1.w};
    int   av[8]  = {a0.x, a0.y, a0.z, a0.w, a1.x, a1.y, a1.z, a1.w};
    float m = NEGV;
    #pragma unroll
    for (int i = 0; i < 8; i++) {
        float x = wh1 + w2v[i];
        x = x > 0.f ? x : ALPHA * x;
        e[i]   = x;
        msk[i] = av[i] > 0;
        float s = msk[i] ? x : NEGV;
        m = fmaxf(m, s);
    }
    // block max
    #pragma unroll
    for (int o = 16; o; o >>= 1) m = fmaxf(m, __shfl_xor_sync(0xffffffffu, m, o));
    if ((tid & 31) == 0) redmax[tid >> 5] = m;
    __syncthreads();
    m = redmax[0];
    #pragma unroll
    for (int i = 1; i < 8; i++) m = fmaxf(m, redmax[i]);

    float p[8];
    float s = 0.f;
    #pragma unroll
    for (int i = 0; i < 8; i++) {
        p[i] = msk[i] ? __expf(e[i] - m) : 0.f;
        s += p[i];
    }
    #pragma unroll
    for (int o = 16; o; o >>= 1) s += __shfl_xor_sync(0xffffffffu, s, o);
    if ((tid & 31) == 0) redsum[tid >> 5] = s;
    __syncthreads();
    s = redsum[0];
    #pragma unroll
    for (int i = 1; i < 8; i++) s += redsum[i];
    float inv = 1.0f / s;

    float4 o0, o1;
    o0.x = p[0] * inv; o0.y = p[1] * inv; o0.z = p[2] * inv; o0.w = p[3] * inv;
    o1.x = p[4] * inv; o1.y = p[5] * inv; o1.z = p[6] * inv; o1.w = p[7] * inv;
    float* dst = attn + (size_t)row * Nq + tid * 8;
    *(float4*)dst       = o0;
    *(float4*)(dst + 4) = o1;
}

// ---------------- K4: out = h + attention @ Wh  (bf16 mma.sync) -------------
__device__ __forceinline__ void ldmA4(uint32_t* a, uint32_t addr) {
    asm volatile("ldmatrix.sync.aligned.m8n8.x4.shared.b16 {%0,%1,%2,%3}, [%4];"
                 : "=r"(a[0]), "=r"(a[1]), "=r"(a[2]), "=r"(a[3]) : "r"(addr));
}
__device__ __forceinline__ void ldmBt2(uint32_t* b, uint32_t addr) {
    asm volatile("ldmatrix.sync.aligned.m8n8.x2.trans.shared.b16 {%0,%1}, [%2];"
                 : "=r"(b[0]), "=r"(b[1]) : "r"(addr));
}
__device__ __forceinline__ void mma16816(float* c, const uint32_t* a, const uint32_t* b) {
    asm volatile("mma.sync.aligned.m16n8k16.row.col.f32.bf16.bf16.f32 "
                 "{%0,%1,%2,%3}, {%4,%5,%6,%7}, {%8,%9}, {%0,%1,%2,%3};"
                 : "+f"(c[0]), "+f"(c[1]), "+f"(c[2]), "+f"(c[3])
                 : "r"(a[0]), "r"(a[1]), "r"(a[2]), "r"(a[3]), "r"(b[0]), "r"(b[1]));
}

#define TM4 128
#define KC4 32
#define AS_STRIDE 40     // bf16 halves (pad 8) -> 80B row, conflict-free ldmatrix
#define BS_STRIDE 136    // bf16 halves (pad 8)

__global__ void __launch_bounds__(512) k_av(const float* __restrict__ attn,
                                            const float* __restrict__ h,
                                            float* __restrict__ out) {
    __shared__ __nv_bfloat16 As[TM4][AS_STRIDE];  // attention tile (bf16) [m][k]
    __shared__ __nv_bfloat16 Bs[KC4][BS_STRIDE];  // Wh tile [k][c]

    const int tid  = threadIdx.x;
    const int lane = tid & 31;
    const int wid  = tid >> 5;          // 0..15
    const int wy   = wid >> 2;          // 0..3  (m block of 32)
    const int wx   = wid & 3;           // 0..3  (n block of 32)
    const int b    = blockIdx.x >> 4;
    const int mt   = blockIdx.x & 15;

    const float* ab           = attn + ((size_t)b * Nq + mt * TM4) * Nq;
    const __nv_bfloat16* whb  = g_Whb + (size_t)b * Nq * Dq;

    float acc[2][4][4];
    #pragma unroll
    for (int t = 0; t < 2; t++)
        #pragma unroll
        for (int u = 0; u < 4; u++)
            #pragma unroll
            for (int q = 0; q < 4; q++) acc[t][u][q] = 0.f;

    uint32_t as0 = (uint32_t)__cvta_generic_to_shared(&As[0][0]);
    uint32_t bs0 = (uint32_t)__cvta_generic_to_shared(&Bs[0][0]);

    const int i0 = tid, i1 = tid + 512;
    const int r0 = i0 >> 3, f0 = i0 & 7;
    const int r1 = i1 >> 3, f1 = i1 & 7;
    const int brow = tid >> 4;          // 0..31  (B tile row)
    const int bcol = (tid & 15) * 8;    // 0..120 (B tile col, 8 bf16 per thread)

    float4 ra0, ra1;
    uint4  rb;
    // prefetch chunk 0
    ra0 = *(const float4*)&ab[(size_t)r0 * Nq + f0 * 4];
    ra1 = *(const float4*)&ab[(size_t)r1 * Nq + f1 * 4];
    rb  = *(const uint4*)(whb + (size_t)brow * Dq + bcol);

    const int NIT = Nq / KC4;   // 64
    for (int it = 0; it < NIT; it++) {
        // stage registers -> smem
        {
            __nv_bfloat162* p = (__nv_bfloat162*)&As[r0][f0 * 4];
            __nv_bfloat162 t0, t1;
            t0.x = __float2bfloat16_rn(ra0.x); t0.y = __float2bfloat16_rn(ra0.y);
            t1.x = __float2bfloat16_rn(ra0.z); t1.y = __float2bfloat16_rn(ra0.w);
            p[0] = t0; p[1] = t1;
            p = (__nv_bfloat162*)&As[r1][f1 * 4];
            t0.x = __float2bfloat16_rn(ra1.x); t0.y = __float2bfloat16_rn(ra1.y);
            t1.x = __float2bfloat16_rn(ra1.z); t1.y = __float2bfloat16_rn(ra1.w);
            p[0] = t0; p[1] = t1;
            *(uint4*)&Bs[brow][bcol] = rb;
        }
        __syncthreads();
        // prefetch next chunk
        if (it + 1 < NIT) {
            int kc = (it + 1) * KC4;
            ra0 = *(const float4*)&ab[(size_t)r0 * Nq + kc + f0 * 4];
            ra1 = *(const float4*)&ab[(size_t)r1 * Nq + kc + f1 * 4];
            rb  = *(const uint4*)(whb + (size_t)(kc + brow) * Dq + bcol);
        }
        // compute: 2 x k16
        #pragma unroll
        for (int kk = 0; kk < KC4; kk += 16) {
            uint32_t afr[2][4];
            #pragma unroll
            for (int t = 0; t < 2; t++) {
                int m = wy * 32 + t * 16 + (lane & 15);
                uint32_t addr = as0 + ((uint32_t)m * AS_STRIDE + kk + ((lane >> 4) << 3)) * 2u;
                ldmA4(afr[t], addr);
            }
            uint32_t bfr[4][2];
            #pragma unroll
            for (int u = 0; u < 4; u++) {
                int k = kk + (lane & 15);
                int n = wx * 32 + u * 8;
                uint32_t addr = bs0 + ((uint32_t)k * BS_STRIDE + n) * 2u;
                ldmBt2(bfr[u], addr);
            }
            #pragma unroll
            for (int t = 0; t < 2; t++)
                #pragma unroll
                for (int u = 0; u < 4; u++)
                    mma16816(acc[t][u], afr[t], bfr[u]);
        }
        __syncthreads();
    }

    // epilogue: out = h + acc (residual)
    #pragma unroll
    for (int t = 0; t < 2; t++) {
        #pragma unroll
        for (int u = 0; u < 4; u++) {
            int r = mt * TM4 + wy * 32 + t * 16 + (lane >> 2);
            int c = wx * 32 + u * 8 + (lane & 3) * 2;
            size_t base = ((size_t)b * Nq + r) * Dq + c;
            float2 hv = *(const float2*)&h[base];
            float2 ov;
            ov.x = hv.x + acc[t][u][0];
            ov.y = hv.y + acc[t][u][1];
            *(float2*)&out[base] = ov;
            size_t base2 = base + (size_t)8 * Dq;
            float2 hv2 = *(const float2*)&h[base2];
            float2 ov2;
            ov2.x = hv2.x + acc[t][u][2];
            ov2.y = hv2.y + acc[t][u][3];
            *(float2*)&out[base2] = ov2;
        }
    }
}

// ---------------------------------------------------------------------------
extern "C" void kernel_launch(void* const* d_in, const int* in_sizes, int n_in,
                              void* d_out, int out_size) {
    const float* h   = (const float*)d_in[0];
    const int*   adj = (const int*)d_in[1];
    const float* W   = (const float*)d_in[2];
    const float* a   = (const float*)d_in[3];
    float* out  = (float*)d_out;
    float* attn = out + (size_t)Bq * Nq * Dq;   // output layout: [out | attention]

    k_wa  <<<1, 128>>>(W, a);
    k_wh12<<<(Bq * Nq) / 8, 256>>>(h);
    k_wh  <<<(Bq * Nq) / TM2, 256>>>(h, W);
    k_soft<<<Bq * Nq, 256>>>(adj, attn);
    k_av  <<<Bq * (Nq / TM4), 512>>>(attn, h, out);
}